// round 16
// baseline (speedup 1.0000x reference)
#include <cuda_runtime.h>
#include <cstdint>

// Fixed shapes from reference setup_inputs
#define BB 4
#define NN 32
#define RR 64
#define HH 480
#define WW 640
#define HWSZ (HH * WW)              // 307200
#define PAIRS (BB * NN)             // 128
#define QUADS (HWSZ / 4)            // 76800 float4 per (b,n) plane

#define GROUPS 8                    // mask groups per batch
#define MPG 4                       // masks per group
#define FAMS (BB * GROUPS)          // 32 (b,group) families
#define GRID 888                    // 148 SMs * 6 (33.5KB smem/block -> 6 resident)

#define TILE_QUADS 256              // 4KB per plane per tile
#define TILE_BYTES (TILE_QUADS * 16)
#define STAGE_BYTES (MPG * TILE_BYTES)       // 16KB prefetched per tile
#define TILES_PER_FAM (QUADS / TILE_QUADS)   // 300

#define MARGIN_RANK 0.1f
#define MARGIN_OCC  0.3f
#define LAMBDA_OCC  1.5f
#define MIN_PIXELS  20.0f

// Zero at module load; last-arriving block resets everything after use (replay-safe).
__device__ float    g_acc[2 * PAIRS];
__device__ unsigned g_ctr[FAMS];
__device__ unsigned g_arrive = 0;

__device__ __forceinline__ void mbar_init(uint32_t addr, uint32_t cnt) {
    asm volatile("mbarrier.init.shared.b64 [%0], %1;" :: "r"(addr), "r"(cnt) : "memory");
}
__device__ __forceinline__ void mbar_expect_tx(uint32_t addr, uint32_t bytes) {
    asm volatile("mbarrier.arrive.expect_tx.shared.b64 _, [%0], %1;"
                 :: "r"(addr), "r"(bytes) : "memory");
}
__device__ __forceinline__ void mbar_wait(uint32_t addr, int parity) {
    asm volatile(
        "{\n\t.reg .pred P;\n\t"
        "W_%=:\n\t"
        "mbarrier.try_wait.parity.acquire.cta.shared::cta.b64 P, [%0], %1, 0x989680;\n\t"
        "@P bra D_%=;\n\t"
        "bra W_%=;\n\t"
        "D_%=:\n\t}"
        :: "r"(addr), "r"(parity) : "memory");
}
__device__ __forceinline__ void tma_1d(uint32_t dst, const void* src, uint32_t bytes, uint32_t mbar) {
    asm volatile(
        "cp.async.bulk.shared::cluster.global.mbarrier::complete_tx::bytes [%0], [%1], %2, [%3];"
        :: "r"(dst), "l"(src), "r"(bytes), "r"(mbar) : "memory");
}

__global__ __launch_bounds__(256, 6) void reldepth_fused_kernel(
    const float* __restrict__ depth,   // (B,1,H,W)
    const float* __restrict__ masks,   // (B,N,H,W)
    const int*   __restrict__ subj,    // (B,R)
    const int*   __restrict__ obj,     // (B,R)
    const int*   __restrict__ rel,     // (B,R)
    const float* __restrict__ conf,    // (B,R)
    float* __restrict__ out)
{
    const int t    = threadIdx.x;
    const int warp = t >> 5;
    const int lane = t & 31;

    const int fam = blockIdx.x & (FAMS - 1);
    const int b   = fam >> 3;          // fam / GROUPS
    const int g   = fam & 7;           // fam % GROUPS

    const float*  mbase = masks + (size_t)(b * NN + g * MPG) * HWSZ;
    const float4* d4    = (const float4*)(depth + (size_t)b * HWSZ);

    __shared__ alignas(128) float4 s_buf[2][MPG][TILE_QUADS];   // 32KB
    __shared__ alignas(8) unsigned long long s_mbar[2];
    __shared__ int s_next;

    const uint32_t mb0 = (uint32_t)__cvta_generic_to_shared(&s_mbar[0]);
    const uint32_t mb1 = (uint32_t)__cvta_generic_to_shared(&s_mbar[1]);

    if (t == 0) { mbar_init(mb0, 1); mbar_init(mb1, 1); }
    __syncthreads();

    // Prologue: steal first tile, kick its TMA
    if (t == 0) s_next = (int)atomicAdd(&g_ctr[fam], 1u);
    __syncthreads();
    int r_cur = s_next;
    __syncthreads();
    if (t == 0 && r_cur < TILES_PER_FAM) {
        mbar_expect_tx(mb0, STAGE_BYTES);
        #pragma unroll
        for (int m = 0; m < MPG; m++)
            tma_1d((uint32_t)__cvta_generic_to_shared(&s_buf[0][m][0]),
                   mbase + (size_t)m * HWSZ + (size_t)r_cur * (TILE_QUADS * 4),
                   TILE_BYTES, mb0);
    }

    int cur = 0;
    int phase[2] = {0, 0};
    float accd[MPG], accc[MPG];
    #pragma unroll
    for (int m = 0; m < MPG; m++) { accd[m] = 0.0f; accc[m] = 0.0f; }

    while (r_cur < TILES_PER_FAM) {
        // Steal next tile; prefetch it into the other buffer (consumed last iter)
        if (t == 0) s_next = (int)atomicAdd(&g_ctr[fam], 1u);
        __syncthreads();
        const int r_next = s_next;
        __syncthreads();
        const int nxt = cur ^ 1;
        if (t == 0 && r_next < TILES_PER_FAM) {
            const uint32_t mbn = nxt ? mb1 : mb0;
            mbar_expect_tx(mbn, STAGE_BYTES);
            #pragma unroll
            for (int m = 0; m < MPG; m++)
                tma_1d((uint32_t)__cvta_generic_to_shared(&s_buf[nxt][m][0]),
                       mbase + (size_t)m * HWSZ + (size_t)r_next * (TILE_QUADS * 4),
                       TILE_BYTES, mbn);
        }

        // Wait for current tile's data, then consume it
        mbar_wait(cur ? mb1 : mb0, phase[cur]);
        phase[cur] ^= 1;

        const float4 dv = __ldg(&d4[r_cur * TILE_QUADS + t]);
        #pragma unroll
        for (int m = 0; m < MPG; m++) {
            const float4 mv = s_buf[cur][m][t];
            if (mv.x > 0.5f) { accc[m] += 1.0f; accd[m] += dv.x; }
            if (mv.y > 0.5f) { accc[m] += 1.0f; accd[m] += dv.y; }
            if (mv.z > 0.5f) { accc[m] += 1.0f; accd[m] += dv.z; }
            if (mv.w > 0.5f) { accc[m] += 1.0f; accd[m] += dv.w; }
        }
        __syncthreads();   // everyone done reading s_buf[cur] before it is refilled

        cur = nxt;
        r_cur = r_next;
    }

    // ---- Reduce accumulators: warp shuffles, then cross-warp in smem ----
    __shared__ float s_red[8][2 * MPG];
    #pragma unroll
    for (int m = 0; m < MPG; m++) {
        float d = accd[m], c = accc[m];
        #pragma unroll
        for (int off = 16; off > 0; off >>= 1) {
            d += __shfl_down_sync(0xFFFFFFFFu, d, off);
            c += __shfl_down_sync(0xFFFFFFFFu, c, off);
        }
        if (lane == 0) { s_red[warp][2 * m] = d; s_red[warp][2 * m + 1] = c; }
    }
    __syncthreads();

    if (t < 2 * MPG) {
        float v = 0.0f;
        #pragma unroll
        for (int w = 0; w < 8; w++) v += s_red[w][t];
        const int m     = t >> 1;
        const int which = t & 1;
        atomicAdd(&g_acc[2 * (b * NN + g * MPG + m) + which], v);
    }

    // ---- Arrival: last block runs the epilogue ----
    __shared__ bool s_last;
    __syncthreads();
    if (t == 0) {
        __threadfence();
        unsigned old = atomicAdd(&g_arrive, 1u);
        s_last = (old == GRID - 1);
        if (s_last) g_arrive = 0;
    }
    __syncthreads();
    if (!s_last) return;

    __threadfence();   // acquire all blocks' atomics

    __shared__ float s_dobj[PAIRS];
    __shared__ float s_cnt[PAIRS];

    if (t < FAMS) g_ctr[t] = 0;    // reset stealing counters for next replay

    if (t < PAIRS) {
        float D = g_acc[2 * t];
        float C = g_acc[2 * t + 1];
        s_dobj[t] = D / fmaxf(C, 1.0f);
        s_cnt[t]  = C;
        g_acc[2 * t]     = 0.0f;   // re-zero for next replay
        g_acc[2 * t + 1] = 0.0f;
    }
    __syncthreads();

    // 256 threads == B*R relations
    const int rb = t / RR;
    const int si = subj[t];
    const int oi = obj[t];
    const int rt = rel[t];
    const float cf = conf[t];

    const int ai = rb * NN + ((rt == 1) ? oi : si);
    const int bi = rb * NN + ((rt == 1) ? si : oi);

    const bool valid = (s_cnt[ai] >= MIN_PIXELS) && (s_cnt[bi] >= MIN_PIXELS);
    const float margin = (rt == 2) ? MARGIN_OCC : MARGIN_RANK;
    const float coeff  = (rt == 2) ? LAMBDA_OCC : 1.0f;
    const float viol = fmaxf(s_dobj[ai] - s_dobj[bi] + margin, 0.0f);

    float tot  = valid ? (coeff * cf * viol) : 0.0f;
    float vcnt = valid ? 1.0f : 0.0f;

    #pragma unroll
    for (int off = 16; off > 0; off >>= 1) {
        tot  += __shfl_down_sync(0xFFFFFFFFu, tot,  off);
        vcnt += __shfl_down_sync(0xFFFFFFFFu, vcnt, off);
    }
    __shared__ float s_t[8];
    __shared__ float s_v[8];
    if (lane == 0) { s_t[warp] = tot; s_v[warp] = vcnt; }
    __syncthreads();
    if (t == 0) {
        float T = 0.f, C = 0.f;
        #pragma unroll
        for (int w = 0; w < 8; w++) { T += s_t[w]; C += s_v[w]; }
        out[0] = (C > 0.0f) ? (T / fmaxf(C, 1.0f)) : 0.0f;
    }
}

extern "C" void kernel_launch(void* const* d_in, const int* in_sizes, int n_in,
                              void* d_out, int out_size)
{
    const float* depth = (const float*)d_in[0];
    const float* masks = (const float*)d_in[1];
    const int*   subj  = (const int*)d_in[2];
    const int*   obj   = (const int*)d_in[3];
    const int*   rel   = (const int*)d_in[4];
    const float* conf  = (const float*)d_in[5];
    float* out = (float*)d_out;

    reldepth_fused_kernel<<<GRID, 256>>>(depth, masks, subj, obj, rel, conf, out);
}